// round 5
// baseline (speedup 1.0000x reference)
#include <cuda_runtime.h>
#include <math.h>
#include <stdint.h>

// ---------------- problem constants ----------------
#define HID 2048
#define NEXP 256
#define NGRP 8
#define TOPG 4
#define TOPK 8
#define RSCALE 2.5f
#define MT 64                  // tokens per CTA
#define KT 32                  // K per smem stage
#define NST (HID / KT)         // 64 stages

// ---------------- smem layout (raw fp32 tiles) ----------------
// row stride 36 floats: bank = (4*row + col) & 31 -> conflict-free frag loads
#define RS 36
#define OFF_BIAS 0
#define OFF_TILES 1024
#define AOFF 0
#define BOFF (MT * RS * 4)                       // 9216
#define STAGE (MT * RS * 4 + NEXP * RS * 4)      // 46080
#define SMEM_TOTAL (OFF_TILES + 2 * STAGE)       // 93184
#define SC_STRIDE 260

#define MMA(d, a, b) asm volatile( \
    "mma.sync.aligned.m16n8k8.row.col.f32.tf32.tf32.f32 " \
    "{%0,%1,%2,%3},{%4,%5,%6,%7},{%8,%9},{%0,%1,%2,%3};" \
    : "+f"((d)[0]), "+f"((d)[1]), "+f"((d)[2]), "+f"((d)[3]) \
    : "r"((a)[0]), "r"((a)[1]), "r"((a)[2]), "r"((a)[3]), \
      "r"((b)[0]), "r"((b)[1]))

#define CPA(dst, src) asm volatile( \
    "cp.async.cg.shared.global [%0], [%1], 16;" :: "r"(dst), "l"(src) : "memory")
#define CPA_COMMIT asm volatile("cp.async.commit_group;" ::: "memory")

static __device__ __forceinline__ uint32_t s2u(const void* p) {
    uint32_t r;
    asm("{ .reg .u64 t; cvta.to.shared.u64 t, %1; cvt.u32.u64 %0, t; }" : "=r"(r) : "l"(p));
    return r;
}

// round-to-nearest tf32 split: v ~= hi + lo, both exactly tf32
static __device__ __forceinline__ void split2(float v, uint32_t& h, uint32_t& l) {
    asm("cvt.rna.tf32.f32 %0, %1;" : "=r"(h) : "f"(v));
    float r = v - __uint_as_float(h);
    asm("cvt.rna.tf32.f32 %0, %1;" : "=r"(l) : "f"(r));
}

// ---------------------------------------------------------------------------
// Fused: 3xTF32 mma.sync GEMM (64 x 256 x 2048 per CTA) with DUAL accumulators
// (hi*hi exact in accH; cross terms in accL) + sigmoid + grouped top-k routing.
// 512 threads, 16 warps, 32x32 warp tiles, 2-stage cp.async pipeline.
// ---------------------------------------------------------------------------
extern "C" __global__ void __launch_bounds__(512, 1)
gate_fused_kernel(const float* __restrict__ x,
                  const float* __restrict__ w,
                  const float* __restrict__ bias,
                  float* __restrict__ out, int N, int with_idx)
{
    extern __shared__ __align__(1024) char smem[];
    const uint32_t sb = s2u(smem);
    const int tid  = threadIdx.x;
    const int wid  = tid >> 5;
    const int lane = tid & 31;
    const int m0   = blockIdx.x * MT;
    const int wm   = wid & 1;      // 2 M-groups of 32 tokens
    const int wn   = wid >> 1;     // 8 N-groups of 32 experts

    float* bs = (float*)(smem + OFF_BIAS);
    if (tid < NEXP) bs[tid] = bias[tid];

    float accH[2][4][4], accL[2][4][4];
    #pragma unroll
    for (int i = 0; i < 2; i++)
        #pragma unroll
        for (int j = 0; j < 4; j++)
            #pragma unroll
            for (int c = 0; c < 4; c++) { accH[i][j][c] = 0.0f; accL[i][j][c] = 0.0f; }

    const int lrow = tid >> 3;       // 0..63
    const int lq   = tid & 7;

    // ---- async load of raw fp32 tiles for stage s ----
    auto ldga = [&](int s) {
        const int k0 = s * KT;
        const uint32_t bufa = sb + OFF_TILES + (s & 1) * STAGE;
        {   // A: 64 rows, 1 float4 per thread
            uint32_t dst = bufa + AOFF + (uint32_t)(lrow * RS + lq * 4) * 4;
            CPA(dst, x + (size_t)(m0 + lrow) * HID + k0 + lq * 4);
        }
        #pragma unroll
        for (int i = 0; i < 4; i++) {   // B: 256 rows, 4 float4 per thread
            int row = lrow + i * 64;
            uint32_t dst = bufa + BOFF + (uint32_t)(row * RS + lq * 4) * 4;
            CPA(dst, w + (size_t)row * HID + k0 + lq * 4);
        }
        CPA_COMMIT;
    };

    const int afo = (wm * 32 + (lane >> 2)) * RS + (lane & 3);
    const int bfo = (wn * 32 + (lane >> 2)) * RS + (lane & 3);

    auto compute = [&](int s) {
        const char* buf = smem + OFF_TILES + (s & 1) * STAGE;
        const float* Ar = (const float*)(buf + AOFF);
        const float* Br = (const float*)(buf + BOFF);
        #pragma unroll
        for (int ks = 0; ks < 4; ks++) {
            const int kb = ks * 8;
            uint32_t ah[2][4], al[2][4];
            #pragma unroll
            for (int mi = 0; mi < 2; mi++) {
                int o = afo + mi * (16 * RS) + kb;
                split2(Ar[o],              ah[mi][0], al[mi][0]);
                split2(Ar[o + 8 * RS],     ah[mi][1], al[mi][1]);
                split2(Ar[o + 4],          ah[mi][2], al[mi][2]);
                split2(Ar[o + 8 * RS + 4], ah[mi][3], al[mi][3]);
            }
            #pragma unroll
            for (int ni = 0; ni < 4; ni++) {
                int o = bfo + ni * (8 * RS) + kb;
                uint32_t bh[2], bl[2];
                split2(Br[o],     bh[0], bl[0]);
                split2(Br[o + 4], bh[1], bl[1]);
                #pragma unroll
                for (int mi = 0; mi < 2; mi++) {
                    MMA(accH[mi][ni], ah[mi], bh);   // exact products
                    MMA(accL[mi][ni], al[mi], bh);   // small terms, small acc
                    MMA(accL[mi][ni], ah[mi], bl);
                }
            }
        }
    };

    // ---- pipelined main loop (2-stage cp.async) ----
    ldga(0);
    for (int s = 0; s < NST; s++) {
        if (s + 1 < NST) {
            ldga(s + 1);
            asm volatile("cp.async.wait_group 1;" ::: "memory");
        } else {
            asm volatile("cp.async.wait_group 0;" ::: "memory");
        }
        __syncthreads();
        compute(s);
        __syncthreads();
    }

    // ---- epilogue: combine acc, +bias, sigmoid (precise), scores overlay ----
    float* sc = (float*)(smem + OFF_TILES);
    #pragma unroll
    for (int mi = 0; mi < 2; mi++) {
        int tr = wm * 32 + mi * 16 + (lane >> 2);
        #pragma unroll
        for (int ni = 0; ni < 4; ni++) {
            int e = wn * 32 + ni * 8 + (lane & 3) * 2;
            float s0 = (accH[mi][ni][0] + accL[mi][ni][0]) + bs[e];
            float s1 = (accH[mi][ni][1] + accL[mi][ni][1]) + bs[e + 1];
            float s2 = (accH[mi][ni][2] + accL[mi][ni][2]) + bs[e];
            float s3 = (accH[mi][ni][3] + accL[mi][ni][3]) + bs[e + 1];
            float2 v0, v1;
            v0.x = 1.0f / (1.0f + expf(-s0));
            v0.y = 1.0f / (1.0f + expf(-s1));
            v1.x = 1.0f / (1.0f + expf(-s2));
            v1.y = 1.0f / (1.0f + expf(-s3));
            *(float2*)&sc[tr * SC_STRIDE + e]       = v0;
            *(float2*)&sc[(tr + 8) * SC_STRIDE + e] = v1;
        }
    }
    __syncthreads();

    // ---- routing: warp per token, 4 tokens per warp ----
    for (int it = 0; it < 4; it++) {
        const int t = wid * 4 + it;
        const float* row = sc + t * SC_STRIDE;

        float orig[NGRP], rsc[NGRP];
        #pragma unroll
        for (int s = 0; s < NGRP; s++) {
            float sg = row[s * 32 + lane];
            orig[s] = sg;
            rsc[s] = sg + bs[s * 32 + lane];
        }

        // group score = top-2 sum (ties -> lower expert index)
        float gs[NGRP];
        #pragma unroll
        for (int g = 0; g < NGRP; g++) {
            float m1 = rsc[g];
            int l1 = lane;
            #pragma unroll
            for (int off = 16; off >= 1; off >>= 1) {
                float ov = __shfl_xor_sync(0xffffffffu, m1, off);
                int ol = __shfl_xor_sync(0xffffffffu, l1, off);
                if (ov > m1 || (ov == m1 && ol < l1)) { m1 = ov; l1 = ol; }
            }
            float v2 = (lane == l1) ? -INFINITY : rsc[g];
            #pragma unroll
            for (int off = 16; off >= 1; off >>= 1)
                v2 = fmaxf(v2, __shfl_xor_sync(0xffffffffu, v2, off));
            gs[g] = m1 + v2;
        }

        // keep top-4 groups (ties -> lower group index)
        float mv[NGRP];
        #pragma unroll
        for (int g = 0; g < NGRP; g++) {
            int cnt = 0;
            #pragma unroll
            for (int h = 0; h < NGRP; h++)
                cnt += (gs[h] > gs[g]) || (gs[h] == gs[g] && h < g);
            mv[g] = (cnt < TOPG) ? rsc[g] : -INFINITY;
        }

        // iterative top-8 (ties -> lower expert index)
        float wsel[TOPK];
        int esel[TOPK];
        #pragma unroll
        for (int k = 0; k < TOPK; k++) {
            float bv2 = -INFINITY; int be = NEXP; float bo = 0.0f;
            #pragma unroll
            for (int s = 0; s < NGRP; s++)
                if (mv[s] > bv2) { bv2 = mv[s]; be = s * 32 + lane; bo = orig[s]; }
            #pragma unroll
            for (int off = 16; off >= 1; off >>= 1) {
                float ov = __shfl_xor_sync(0xffffffffu, bv2, off);
                int oe = __shfl_xor_sync(0xffffffffu, be, off);
                float oo = __shfl_xor_sync(0xffffffffu, bo, off);
                if (ov > bv2 || (ov == bv2 && oe < be)) { bv2 = ov; be = oe; bo = oo; }
            }
            wsel[k] = bo;
            esel[k] = be;
            if ((be & 31) == lane) {
                int bslot = be >> 5;
                #pragma unroll
                for (int s = 0; s < NGRP; s++)
                    if (s == bslot) mv[s] = -INFINITY;
            }
        }

        float tot = 0.0f;
        #pragma unroll
        for (int k = 0; k < TOPK; k++) tot += wsel[k];
        float inv = RSCALE / tot;

        const int gt = m0 + t;
        #pragma unroll
        for (int k = 0; k < TOPK; k++) {
            if (lane == k) {
                out[(size_t)gt * TOPK + k] = wsel[k] * inv;
                if (with_idx)
                    out[(size_t)N * TOPK + (size_t)gt * TOPK + k] = (float)esel[k];
            }
        }
    }
}

// ---------------------------------------------------------------------------
extern "C" void kernel_launch(void* const* d_in, const int* in_sizes, int n_in,
                              void* d_out, int out_size)
{
    const float* x    = (const float*)d_in[0];
    const float* w    = (const float*)d_in[1];
    const float* bias = (const float*)d_in[2];
    float* out = (float*)d_out;

    int N = in_sizes[0] / HID;
    int with_idx = (out_size >= 2 * N * TOPK) ? 1 : 0;

    cudaFuncSetAttribute(gate_fused_kernel,
                         cudaFuncAttributeMaxDynamicSharedMemorySize, SMEM_TOTAL);
    gate_fused_kernel<<<N / MT, 512, SMEM_TOTAL>>>(x, w, bias, out, N, with_idx);
}